// round 3
// baseline (speedup 1.0000x reference)
#include <cuda_runtime.h>
#include <cstddef>

#define TT 1024
#define BB 8
#define VV 32000
#define EE 32
#define HH 8
#define NROWS (TT*BB)      // 8192
#define VBLK  25           // grid.x of pass kernels
#define VITER 10           // v-chunks per block
#define VCHUNK 128         // 32 lanes * 4

// ---------------- scratch (device globals; no allocation) ----------------
__device__ float g_xp[2*TT*BB*HH];     // [dir][t][b][h]  input projections (+both biases)
__device__ float g_totalH[TT*16*BB];   // [t][d][b]  d<8: forward h1, d>=8: backward h2
__device__ float g_partial[VBLK*NROWS];// per v-block partial sum-of-exp, deterministic
__device__ float g_rowstat[NROWS];     // log(sum exp) per row

// packed f32x2 FMA (sm_100+): 2 scalar FMAs per instruction
__device__ __forceinline__ float2 f2fma(float2 a, float2 b, float2 c) {
    float2 d;
    asm("fma.rn.f32x2 %0, %1, %2, %3;"
        : "=l"(*reinterpret_cast<unsigned long long*>(&d))
        : "l"(*reinterpret_cast<unsigned long long*>(&a)),
          "l"(*reinterpret_cast<unsigned long long*>(&b)),
          "l"(*reinterpret_cast<unsigned long long*>(&c)));
    return d;
}

// ---------------- kernel 1: embedding gather + x-projections ----------------
__global__ void k_embed(const int* __restrict__ x, const float* __restrict__ emb,
                        const float* __restrict__ Wx1, const float* __restrict__ bx1,
                        const float* __restrict__ bh1,
                        const float* __restrict__ Wx2, const float* __restrict__ bx2,
                        const float* __restrict__ bh2) {
    int tid = blockIdx.x * blockDim.x + threadIdx.x;   // (t,b) flat
    if (tid >= NROWS) return;
    int idx = x[tid];
    const float4* em = (const float4*)(emb + (size_t)idx * EE);
    float e[EE];
    #pragma unroll
    for (int q = 0; q < 8; q++) {
        float4 v = __ldg(em + q);
        e[4*q] = v.x; e[4*q+1] = v.y; e[4*q+2] = v.z; e[4*q+3] = v.w;
    }
    #pragma unroll
    for (int j = 0; j < HH; j++) {
        float s1 = bx1[j] + bh1[j];
        float s2 = bx2[j] + bh2[j];
        #pragma unroll
        for (int k = 0; k < EE; k++) {
            s1 = fmaf(e[k], __ldg(Wx1 + k*HH + j), s1);
            s2 = fmaf(e[k], __ldg(Wx2 + k*HH + j), s2);
        }
        g_xp[tid*HH + j] = s1;
        g_xp[TT*BB*HH + tid*HH + j] = s2;
    }
}

// ---------------- kernel 2: the two sequential RNNs ----------------
// 16 independent chains: thread = (dir, b). Wh lives in registers.
// Emits h BEFORE the update (matches the reference scan).
__global__ void k_rnn(const float* __restrict__ Wh1, const float* __restrict__ Wh2) {
    int tid = threadIdx.x;
    if (tid >= 16) return;
    int dir = tid >> 3, b = tid & 7;
    const float* Wh = dir ? Wh2 : Wh1;
    float w[HH][HH];
    #pragma unroll
    for (int i = 0; i < HH; i++)
        #pragma unroll
        for (int j = 0; j < HH; j++) w[i][j] = __ldg(Wh + i*HH + j);

    const float* xp = g_xp + dir * (TT*BB*HH);
    float h[HH];
    #pragma unroll
    for (int j = 0; j < HH; j++) h[j] = 0.f;

    for (int s = 0; s < TT; s++) {
        int t = dir ? (TT - 1 - s) : s;
        // emit pre-update hidden state
        float* hp = g_totalH + (t*16 + dir*8) * BB + b;
        #pragma unroll
        for (int j = 0; j < HH; j++) hp[j*BB] = h[j];
        // load x projection for this step
        const float4* xr = (const float4*)(xp + (t*BB + b) * HH);
        float4 xa = xr[0], xb = xr[1];
        float xv[HH] = {xa.x, xa.y, xa.z, xa.w, xb.x, xb.y, xb.z, xb.w};
        float nh[HH];
        #pragma unroll
        for (int j = 0; j < HH; j++) {
            float t0 = fmaf(h[1], w[1][j], h[0]*w[0][j]);
            float t1 = fmaf(h[3], w[3][j], h[2]*w[2][j]);
            float t2 = fmaf(h[5], w[5][j], h[4]*w[4][j]);
            float t3 = fmaf(h[7], w[7][j], h[6]*w[6][j]);
            float z  = xv[j] + ((t0 + t1) + (t2 + t3));
            nh[j] = __fdividef(1.f, 1.f + __expf(-z));
        }
        #pragma unroll
        for (int j = 0; j < HH; j++) h[j] = nh[j];
    }
}

// ---------------- pass kernels: logits GEMM + softmax stats / output ----------------
// Block = (32,8). Covers 4 t-values x 8 batch = 32 rows, and VITER*128 v.
// Thread: 2 row-pairs (f32x2-packed), 4 consecutive v per inner iter.
template <bool PASS1>
__global__ __launch_bounds__(256) void k_pass(const float* __restrict__ W,
                                              float* __restrict__ out) {
    int tx = threadIdx.x;            // 0..31 : v lane
    int ty = threadIdx.y;            // 0..7  : row group (one warp each)
    int t  = blockIdx.y * 4 + (ty >> 1);
    int b0 = (ty & 1) * 4;
    int row0 = t * BB + b0;

    // register-cache hidden state for this thread's 4 rows, pair-packed
    float2 hA[16], hB[16];
    const float* hp = g_totalH + t * 16 * BB;
    #pragma unroll
    for (int d = 0; d < 16; d++) {
        hA[d] = *(const float2*)(hp + d*BB + b0);
        hB[d] = *(const float2*)(hp + d*BB + b0 + 2);
    }

    float st0 = 0.f, st1 = 0.f, st2 = 0.f, st3 = 0.f;
    if (!PASS1) {
        float4 st = *(const float4*)(g_rowstat + row0);
        st0 = st.x; st1 = st.y; st2 = st.z; st3 = st.w;
    }

    float sA0 = 0.f, sA1 = 0.f, sB0 = 0.f, sB1 = 0.f;
    int vbase = blockIdx.x * (VCHUNK * VITER) + tx * 4;

    for (int it = 0; it < VITER; it++) {
        int v = vbase + it * VCHUNK;
        float2 aA[4], aB[4];
        #pragma unroll
        for (int k = 0; k < 4; k++) { aA[k] = make_float2(0.f,0.f); aB[k] = make_float2(0.f,0.f); }

        #pragma unroll
        for (int d = 0; d < 16; d++) {
            float4 wq = __ldg((const float4*)(W + (size_t)d * VV + v));
            float2 w0 = make_float2(wq.x, wq.x);
            float2 w1 = make_float2(wq.y, wq.y);
            float2 w2 = make_float2(wq.z, wq.z);
            float2 w3 = make_float2(wq.w, wq.w);
            aA[0] = f2fma(hA[d], w0, aA[0]);  aB[0] = f2fma(hB[d], w0, aB[0]);
            aA[1] = f2fma(hA[d], w1, aA[1]);  aB[1] = f2fma(hB[d], w1, aB[1]);
            aA[2] = f2fma(hA[d], w2, aA[2]);  aB[2] = f2fma(hB[d], w2, aB[2]);
            aA[3] = f2fma(hA[d], w3, aA[3]);  aB[3] = f2fma(hB[d], w3, aB[3]);
        }

        if (PASS1) {
            #pragma unroll
            for (int k = 0; k < 4; k++) {
                sA0 += __expf(aA[k].x);  sA1 += __expf(aA[k].y);
                sB0 += __expf(aB[k].x);  sB1 += __expf(aB[k].y);
            }
        } else {
            float4 o;
            o = make_float4(aA[0].x-st0, aA[1].x-st0, aA[2].x-st0, aA[3].x-st0);
            *(float4*)(out + (size_t)(row0    ) * VV + v) = o;
            o = make_float4(aA[0].y-st1, aA[1].y-st1, aA[2].y-st1, aA[3].y-st1);
            *(float4*)(out + (size_t)(row0 + 1) * VV + v) = o;
            o = make_float4(aB[0].x-st2, aB[1].x-st2, aB[2].x-st2, aB[3].x-st2);
            *(float4*)(out + (size_t)(row0 + 2) * VV + v) = o;
            o = make_float4(aB[0].y-st3, aB[1].y-st3, aB[2].y-st3, aB[3].y-st3);
            *(float4*)(out + (size_t)(row0 + 3) * VV + v) = o;
        }
    }

    if (PASS1) {
        #pragma unroll
        for (int m = 16; m >= 1; m >>= 1) {
            sA0 += __shfl_xor_sync(0xffffffffu, sA0, m);
            sA1 += __shfl_xor_sync(0xffffffffu, sA1, m);
            sB0 += __shfl_xor_sync(0xffffffffu, sB0, m);
            sB1 += __shfl_xor_sync(0xffffffffu, sB1, m);
        }
        if (tx == 0) {
            float* p = g_partial + (size_t)blockIdx.x * NROWS + row0;
            p[0] = sA0; p[1] = sA1; p[2] = sB0; p[3] = sB1;
        }
    }
}

// ---------------- kernel: reduce partials -> log-sum-exp per row ----------------
__global__ void k_stat() {
    int r = blockIdx.x * blockDim.x + threadIdx.x;
    if (r >= NROWS) return;
    float s = 0.f;
    #pragma unroll
    for (int i = 0; i < VBLK; i++) s += g_partial[i * NROWS + r];
    g_rowstat[r] = logf(s);
}

// ---------------- launch ----------------
extern "C" void kernel_launch(void* const* d_in, const int* in_sizes, int n_in,
                              void* d_out, int out_size) {
    const int*   x   = (const int*)  d_in[0];
    const float* emb = (const float*)d_in[1];
    const float* Wx1 = (const float*)d_in[2];
    const float* bx1 = (const float*)d_in[3];
    const float* Wh1 = (const float*)d_in[4];
    const float* bh1 = (const float*)d_in[5];
    const float* Wx2 = (const float*)d_in[6];
    const float* bx2 = (const float*)d_in[7];
    const float* Wh2 = (const float*)d_in[8];
    const float* bh2 = (const float*)d_in[9];
    const float* Wo  = (const float*)d_in[10];
    float* out = (float*)d_out;

    k_embed<<<(NROWS + 255)/256, 256>>>(x, emb, Wx1, bx1, bh1, Wx2, bx2, bh2);
    k_rnn<<<1, 32>>>(Wh1, Wh2);
    dim3 grd(VBLK, TT/4), blk(32, 8);
    k_pass<true ><<<grd, blk>>>(Wo, nullptr);
    k_stat<<<(NROWS + 255)/256, 256>>>();
    k_pass<false><<<grd, blk>>>(Wo, out);
}

// round 4
// speedup vs baseline: 1.2998x; 1.2998x over previous
#include <cuda_runtime.h>
#include <cstddef>

#define TT 1024
#define BB 8
#define VV 32000
#define EE 32
#define HH 8
#define NROWS (TT*BB)      // 8192
#define VBLK  25           // grid.x of pass kernels
#define VITER 10           // iters per block; per iter each warp covers 128 v

// ---------------- scratch (device globals; no allocation) ----------------
__device__ float  g_xp[2*TT*BB*HH];      // [dir][t][b][h]  input projections (+both biases)
__device__ float  g_totalH[TT*16*BB];    // [t][d][b]  d<8: forward h1, d>=8: backward h2
__device__ float  g_partial[VBLK*NROWS]; // per v-block partial sum-of-exp (deterministic)
__device__ float  g_rowstat[NROWS];      // log(sum exp) per row
__device__ float2 g_W2[16*VV];           // tiled tf32 (hi,lo) pairs of output weights, 4 MB

// tf32 round (rna)
__device__ __forceinline__ unsigned tf32_of(float x) {
    unsigned r;
    asm("cvt.rna.tf32.f32 %0, %1;" : "=r"(r) : "f"(x));
    return r;
}

// m16n8k8 tf32 mma, D += A*B (C aliased to D)
__device__ __forceinline__ void mma_tf32(float& d0, float& d1, float& d2, float& d3,
                                         unsigned a0, unsigned a1, unsigned a2, unsigned a3,
                                         unsigned b0, unsigned b1) {
    asm("mma.sync.aligned.m16n8k8.row.col.f32.tf32.tf32.f32 "
        "{%0,%1,%2,%3}, {%4,%5,%6,%7}, {%8,%9}, {%0,%1,%2,%3};"
        : "+f"(d0), "+f"(d1), "+f"(d2), "+f"(d3)
        : "r"(a0), "r"(a1), "r"(a2), "r"(a3), "r"(b0), "r"(b1));
}

// ---------------- kernel 0: W -> tiled tf32 hi/lo pairs ----------------
// Layout: for v-tile vt (8 v), all 16 k rows contiguous: g_W2[(vt*16 + k)*8 + (v&7)]
__global__ void k_prep(const float* __restrict__ Wo) {
    int v = blockIdx.x * 256 + threadIdx.x;   // grid.x = 125
    int k = blockIdx.y;                        // 16
    float x = __ldg(Wo + (size_t)k * VV + v);
    unsigned hb = tf32_of(x);
    float hf = __uint_as_float(hb);
    unsigned lb = tf32_of(x - hf);
    g_W2[((v >> 3) * 16 + k) * 8 + (v & 7)] = make_float2(hf, __uint_as_float(lb));
}

// ---------------- kernel 1: embedding gather + x-projections ----------------
__global__ void k_embed(const int* __restrict__ x, const float* __restrict__ emb,
                        const float* __restrict__ Wx1, const float* __restrict__ bx1,
                        const float* __restrict__ bh1,
                        const float* __restrict__ Wx2, const float* __restrict__ bx2,
                        const float* __restrict__ bh2) {
    int tid = blockIdx.x * blockDim.x + threadIdx.x;   // (t,b) flat
    if (tid >= NROWS) return;
    int idx = x[tid];
    const float4* em = (const float4*)(emb + (size_t)idx * EE);
    float e[EE];
    #pragma unroll
    for (int q = 0; q < 8; q++) {
        float4 v = __ldg(em + q);
        e[4*q] = v.x; e[4*q+1] = v.y; e[4*q+2] = v.z; e[4*q+3] = v.w;
    }
    #pragma unroll
    for (int j = 0; j < HH; j++) {
        float s1 = bx1[j] + bh1[j];
        float s2 = bx2[j] + bh2[j];
        #pragma unroll
        for (int k = 0; k < EE; k++) {
            s1 = fmaf(e[k], __ldg(Wx1 + k*HH + j), s1);
            s2 = fmaf(e[k], __ldg(Wx2 + k*HH + j), s2);
        }
        g_xp[tid*HH + j] = s1;
        g_xp[TT*BB*HH + tid*HH + j] = s2;
    }
}

// ---------------- kernel 2: the two sequential RNNs ----------------
// 4 blocks x 32 threads. lane = chainLocal*8 + j; 4 chains per warp.
// h exchanged via shfl; xp loads prefetched 4 steps ahead.
// Emits h BEFORE the update (matches the reference scan).
__global__ void k_rnn(const float* __restrict__ Wh1, const float* __restrict__ Wh2) {
    int lane = threadIdx.x;
    int j = lane & 7;
    int c = blockIdx.x * 4 + (lane >> 3);   // chain id 0..15
    int dir = c >> 3, b = c & 7;
    int grp = lane & ~7;                    // base lane of this chain's group
    const float* Wh = dir ? Wh2 : Wh1;
    float w[HH];
    #pragma unroll
    for (int k = 0; k < HH; k++) w[k] = __ldg(Wh + k*HH + j);

    const float* xp = g_xp + dir * (TT*BB*HH);
    float h = 0.f;

    // depth-4 prefetch ring
    float pf[4];
    #pragma unroll
    for (int p = 0; p < 4; p++) {
        int t = dir ? (TT - 1 - p) : p;
        pf[p] = __ldg(xp + (t*BB + b) * HH + j);
    }

    #pragma unroll 4
    for (int s = 0; s < TT; s++) {
        int slot = s & 3;
        float xv = pf[slot];
        if (s + 4 < TT) {
            int t4 = dir ? (TT - 1 - (s + 4)) : (s + 4);
            pf[slot] = __ldg(xp + (t4*BB + b) * HH + j);
        }
        int t = dir ? (TT - 1 - s) : s;
        // emit pre-update hidden state
        g_totalH[(t*16 + dir*8 + j) * BB + b] = h;
        // z_j = xv + sum_k h_k * Wh[k][j]   (tree form)
        float h0 = __shfl_sync(0xffffffffu, h, grp + 0);
        float h1 = __shfl_sync(0xffffffffu, h, grp + 1);
        float h2 = __shfl_sync(0xffffffffu, h, grp + 2);
        float h3 = __shfl_sync(0xffffffffu, h, grp + 3);
        float h4 = __shfl_sync(0xffffffffu, h, grp + 4);
        float h5 = __shfl_sync(0xffffffffu, h, grp + 5);
        float h6 = __shfl_sync(0xffffffffu, h, grp + 6);
        float h7 = __shfl_sync(0xffffffffu, h, grp + 7);
        float t0 = fmaf(h1, w[1], h0 * w[0]);
        float t1 = fmaf(h3, w[3], h2 * w[2]);
        float t2 = fmaf(h5, w[5], h4 * w[4]);
        float t3 = fmaf(h7, w[7], h6 * w[6]);
        float z  = xv + ((t0 + t1) + (t2 + t3));
        h = __fdividef(1.f, 1.f + __expf(-z));
    }
}

// ---------------- pass kernels: tf32 3x mma GEMM + softmax stats / output ----------------
// Block = 256 thr (8 warps). Warp w owns 16 rows (rowBase = by*128 + w*16).
// Per iter each warp covers 128 v (16 n8-tiles); VITER iters per block.
template <bool PASS1>
__global__ __launch_bounds__(256) void k_pass(float* __restrict__ out) {
    int lane = threadIdx.x & 31, w = threadIdx.x >> 5;
    int g = lane >> 2, q = lane & 3;
    int rowBase = blockIdx.y * 128 + w * 16;

    // A fragments (hi/lo), loaded once. a0:(g,q) a1:(g+8,q) a2:(g,q+4) a3:(g+8,q+4)
    unsigned ah[2][4], al[2][4];
    #pragma unroll
    for (int kt = 0; kt < 2; kt++) {
        #pragma unroll
        for (int jj = 0; jj < 4; jj++) {
            int r = g + (jj & 1) * 8;
            int k = kt * 8 + q + ((jj >> 1) ? 4 : 0);
            int grow = rowBase + r, t = grow >> 3, b = grow & 7;
            float v = g_totalH[(t*16 + k) * BB + b];
            unsigned hb = tf32_of(v);
            ah[kt][jj] = hb;
            al[kt][jj] = tf32_of(v - __uint_as_float(hb));
        }
    }

    float st0 = 0.f, st1 = 0.f;
    if (!PASS1) {
        st0 = g_rowstat[rowBase + g];
        st1 = g_rowstat[rowBase + g + 8];
    }

    float sum0 = 0.f, sum1 = 0.f;
    int vt0 = blockIdx.x * (VITER * 16);   // first v-tile index of this block

    for (int it = 0; it < VITER; it++) {
        #pragma unroll
        for (int nt = 0; nt < 16; nt++) {
            int vt = vt0 + it * 16 + nt;
            const float2* Bt = g_W2 + (size_t)vt * 16 * 8;
            float d0 = 0.f, d1 = 0.f, d2 = 0.f, d3 = 0.f;
            #pragma unroll
            for (int kt = 0; kt < 2; kt++) {
                float2 B0 = __ldg(Bt + (kt*8 + q    ) * 8 + g);
                float2 B1 = __ldg(Bt + (kt*8 + q + 4) * 8 + g);
                unsigned b0h = __float_as_uint(B0.x), b0l = __float_as_uint(B0.y);
                unsigned b1h = __float_as_uint(B1.x), b1l = __float_as_uint(B1.y);
                mma_tf32(d0,d1,d2,d3, ah[kt][0],ah[kt][1],ah[kt][2],ah[kt][3], b0h,b1h);
                mma_tf32(d0,d1,d2,d3, ah[kt][0],ah[kt][1],ah[kt][2],ah[kt][3], b0l,b1l);
                mma_tf32(d0,d1,d2,d3, al[kt][0],al[kt][1],al[kt][2],al[kt][3], b0h,b1h);
            }
            if (PASS1) {
                sum0 += __expf(d0) + __expf(d1);
                sum1 += __expf(d2) + __expf(d3);
            } else {
                int vcol = vt * 8 + q * 2;
                *(float2*)(out + (size_t)(rowBase + g    ) * VV + vcol) = make_float2(d0 - st0, d1 - st0);
                *(float2*)(out + (size_t)(rowBase + g + 8) * VV + vcol) = make_float2(d2 - st1, d3 - st1);
            }
        }
    }

    if (PASS1) {
        // reduce across the 4 lanes of each row-group (q dimension)
        sum0 += __shfl_xor_sync(0xffffffffu, sum0, 1);
        sum0 += __shfl_xor_sync(0xffffffffu, sum0, 2);
        sum1 += __shfl_xor_sync(0xffffffffu, sum1, 1);
        sum1 += __shfl_xor_sync(0xffffffffu, sum1, 2);
        if (q == 0) {
            g_partial[(size_t)blockIdx.x * NROWS + rowBase + g    ] = sum0;
            g_partial[(size_t)blockIdx.x * NROWS + rowBase + g + 8] = sum1;
        }
    }
}

// ---------------- kernel: reduce partials -> log-sum-exp per row ----------------
__global__ void k_stat() {
    int r = blockIdx.x * blockDim.x + threadIdx.x;
    if (r >= NROWS) return;
    float s = 0.f;
    #pragma unroll
    for (int i = 0; i < VBLK; i++) s += g_partial[i * NROWS + r];
    g_rowstat[r] = logf(s);
}

// ---------------- launch ----------------
extern "C" void kernel_launch(void* const* d_in, const int* in_sizes, int n_in,
                              void* d_out, int out_size) {
    const int*   x   = (const int*)  d_in[0];
    const float* emb = (const float*)d_in[1];
    const float* Wx1 = (const float*)d_in[2];
    const float* bx1 = (const float*)d_in[3];
    const float* Wh1 = (const float*)d_in[4];
    const float* bh1 = (const float*)d_in[5];
    const float* Wx2 = (const float*)d_in[6];
    const float* bx2 = (const float*)d_in[7];
    const float* Wh2 = (const float*)d_in[8];
    const float* bh2 = (const float*)d_in[9];
    const float* Wo  = (const float*)d_in[10];
    float* out = (float*)d_out;

    dim3 gprep(125, 16);
    k_prep<<<gprep, 256>>>(Wo);
    k_embed<<<(NROWS + 255)/256, 256>>>(x, emb, Wx1, bx1, bh1, Wx2, bx2, bh2);
    k_rnn<<<4, 32>>>(Wh1, Wh2);
    dim3 grd(VBLK, NROWS/128), blk(256);
    k_pass<true ><<<grd, blk>>>(nullptr);
    k_stat<<<(NROWS + 255)/256, 256>>>();
    k_pass<false><<<grd, blk>>>(out);
}